// round 12
// baseline (speedup 1.0000x reference)
#include <cuda_runtime.h>
#include <cuda_fp16.h>
#include <math.h>

// Problem-shape constants (padded)
#define NMAX 100352
#define GMAX 512
#define DPAD 128          // max supported in-degree (data is ~Poisson(32))

// Scratch (device globals; allocation-free per harness rules)
__device__ __align__(128) __half g_xh16[NMAX * 64];   // transformed features (fp16)
__device__ __align__(128) float g_out[NMAX * 64];     // raw aggregation output (pre-bias, pre-BN)
__device__ __align__(128) float g_als[NMAX * 2];
__device__ __align__(128) float g_ald[NMAX * 2];
__device__ __align__(128) float g_bnpart1[32 * 128];
__device__ __align__(128) float g_bnpart2[32 * 128];
__device__ __align__(128) float g_bnstat1[128];
__device__ __align__(128) float g_bnstat2[128];
__device__ __align__(128) float g_comb[GMAX * 128];
// bucket-CSR scratch
__device__ __align__(128) int g_cnt[NMAX];
__device__ __align__(128) int g_ebkt[NMAX * DPAD];

__device__ __forceinline__ float lrelu(float z) { return z > 0.f ? z : 0.2f * z; }
__device__ __forceinline__ float elu(float z) { return z > 0.f ? z : expm1f(z); }

// L1-bypass (cache-global) loads for zero-reuse streams
__device__ __forceinline__ uint4 ldcg_u4(const uint4* p) {
    uint4 v;
    asm("ld.global.cg.v4.u32 {%0,%1,%2,%3}, [%4];"
        : "=r"(v.x), "=r"(v.y), "=r"(v.z), "=r"(v.w) : "l"(p));
    return v;
}
__device__ __forceinline__ float2 ldcg_f2(const float2* p) {
    float2 v;
    asm("ld.global.cg.v2.f32 {%0,%1}, [%2];" : "=f"(v.x), "=f"(v.y) : "l"(p));
    return v;
}
__device__ __forceinline__ float ldcg_f(const float* p) {
    float v;
    asm("ld.global.cg.f32 %0, [%1];" : "=f"(v) : "l"(p));
    return v;
}
__device__ __forceinline__ int ldcg_i(const int* p) {
    int v;
    asm("ld.global.cg.s32 %0, [%1];" : "=r"(v) : "l"(p));
    return v;
}

// ---------------- bucket build ----------------
__global__ void cnt_zero_kernel(int N) {
    int i = blockIdx.x * blockDim.x + threadIdx.x;
    if (i < 4096) { g_bnpart1[i] = 0.f; g_bnpart2[i] = 0.f; }
    if (i < N) g_cnt[i] = 0;
}

// single-pass padded bucket scatter: 4 edges per thread via int4
__global__ void bucket_scatter_kernel(const int* __restrict__ ei, int E) {
    int e4 = blockIdx.x * blockDim.x + threadIdx.x;
    int nq = E >> 2;
    if (e4 < nq) {
        int4 s = __ldg(&((const int4*)ei)[e4]);
        int4 d = __ldg(&((const int4*)(ei + E))[e4]);
        int p0 = atomicAdd(&g_cnt[d.x], 1);
        int p1 = atomicAdd(&g_cnt[d.y], 1);
        int p2 = atomicAdd(&g_cnt[d.z], 1);
        int p3 = atomicAdd(&g_cnt[d.w], 1);
        if (p0 < DPAD) g_ebkt[(d.x << 7) + p0] = s.x;
        if (p1 < DPAD) g_ebkt[(d.y << 7) + p1] = s.y;
        if (p2 < DPAD) g_ebkt[(d.z << 7) + p2] = s.z;
        if (p3 < DPAD) g_ebkt[(d.w << 7) + p3] = s.w;
    } else if (e4 == nq) {
        for (int e = nq * 4; e < E; e++) {
            int s = __ldg(&ei[e]);
            int d = __ldg(&ei[E + e]);
            int pos = atomicAdd(&g_cnt[d], 1);
            if (pos < DPAD) g_ebkt[(d << 7) + pos] = s;
        }
    }
}

// ---------------- fused GEMM: 128x64 tile, 256 threads, 8x4 tile, fp16 A smem ---------------
// EMB=true : src = x [N,4]; A row = elu(x @ W_emb + b_emb)   (embed fused into fill)
// EMB=false: src = g_out;   A row = elu(BN(g_out + bias_prev))
// dynamic smem: As16 (64x128 half, 16KB) | Ws (64x64 f32, 16KB) | s_sc[64] | s_off[64]
template <int H, bool EMB>
__global__ __launch_bounds__(256) void gemm_fused_kernel(
        const float* __restrict__ W,
        const float* __restrict__ a_src, const float* __restrict__ a_dst,
        const float* __restrict__ src,
        const float* __restrict__ We_or_bias,   // W_emb (EMB) | bias_prev (BN)
        const float* __restrict__ be_or_gamma,  // b_emb (EMB) | gamma (BN)
        const float* __restrict__ beta,
        const float* __restrict__ stat, int N) {
    extern __shared__ float smem[];
    __half* As16 = (__half*)smem;          // 64 x 128 halfs = 16KB
    float* Ws = smem + 4096;               // byte offset 16384
    float* s_sc = Ws + 4096;
    float* s_off = s_sc + 64;

    int row0 = blockIdx.x * 128;
    int tid = threadIdx.x;  // 256

    if (!EMB) {
        if (tid < 64) {
            float invN = 1.f / (float)N;
            float mean = stat[tid] * invN;
            float var = stat[64 + tid] * invN - mean * mean;
            float scv = be_or_gamma[tid] * rsqrtf(var + 1e-5f);
            s_sc[tid] = scv;
            s_off[tid] = (We_or_bias[tid] - mean) * scv + beta[tid];
        }
        __syncthreads();
    }

    const float4* W4 = (const float4*)W;
    float4* Ws4 = (float4*)Ws;
#pragma unroll
    for (int i = tid; i < 1024; i += 256) Ws4[i] = W4[i];
#pragma unroll
    for (int i = tid; i < 2048; i += 256) {
        int r = i & 127, kq = i >> 7;
        int n = row0 + r;
        float4 v = make_float4(0.f, 0.f, 0.f, 0.f);
        if (n < N) {
            if (EMB) {
                float4 xv = __ldg(&((const float4*)src)[n]);
                int c = kq * 4;
#pragma unroll
                for (int j = 0; j < 4; j++) {
                    float t = __ldg(&be_or_gamma[c + j])
                            + xv.x * __ldg(&We_or_bias[c + j])
                            + xv.y * __ldg(&We_or_bias[64 + c + j])
                            + xv.z * __ldg(&We_or_bias[128 + c + j])
                            + xv.w * __ldg(&We_or_bias[192 + c + j]);
                    (&v.x)[j] = elu(t);
                }
            } else {
                v = ((const float4*)src)[n * 16 + kq];
                int c = kq * 4;
                v.x = elu(v.x * s_sc[c + 0] + s_off[c + 0]);
                v.y = elu(v.y * s_sc[c + 1] + s_off[c + 1]);
                v.z = elu(v.z * s_sc[c + 2] + s_off[c + 2]);
                v.w = elu(v.w * s_sc[c + 3] + s_off[c + 3]);
            }
        }
        As16[(kq * 4 + 0) * 128 + r] = __float2half(v.x);
        As16[(kq * 4 + 1) * 128 + r] = __float2half(v.y);
        As16[(kq * 4 + 2) * 128 + r] = __float2half(v.z);
        As16[(kq * 4 + 3) * 128 + r] = __float2half(v.w);
    }
    __syncthreads();

    int cg = tid & 15;
    int c0 = cg * 4;
    int r0 = (tid >> 4) * 8;
    float acc[8][4];
#pragma unroll
    for (int i = 0; i < 8; i++)
#pragma unroll
        for (int j = 0; j < 4; j++) acc[i][j] = 0.f;

#pragma unroll 4
    for (int k = 0; k < 64; k++) {
        float4 wv = *(const float4*)&Ws[k * 64 + c0];
        uint4 av = *(const uint4*)&As16[k * 128 + r0];   // 8 halfs
        float2 f0 = __half22float2(*(__half2*)&av.x);
        float2 f1 = __half22float2(*((__half2*)&av.x + 1));
        float2 f2 = __half22float2(*(__half2*)&av.z);
        float2 f3 = __half22float2(*((__half2*)&av.z + 1));
        float ar[8] = {f0.x, f0.y, f1.x, f1.y, f2.x, f2.y, f3.x, f3.y};
#pragma unroll
        for (int i = 0; i < 8; i++) {
            acc[i][0] = fmaf(ar[i], wv.x, acc[i][0]);
            acc[i][1] = fmaf(ar[i], wv.y, acc[i][1]);
            acc[i][2] = fmaf(ar[i], wv.z, acc[i][2]);
            acc[i][3] = fmaf(ar[i], wv.w, acc[i][3]);
        }
    }

    // store fp16 features; compute attention partials
    float a_s0 = a_src[c0], a_s1 = a_src[c0 + 1], a_s2 = a_src[c0 + 2], a_s3 = a_src[c0 + 3];
    float a_d0 = a_dst[c0], a_d1 = a_dst[c0 + 1], a_d2 = a_dst[c0 + 2], a_d3 = a_dst[c0 + 3];
    float pS[8], pD[8];
#pragma unroll
    for (int i = 0; i < 8; i++) {
        int n = row0 + r0 + i;
        if (n < N) {
            __half2 h01 = __floats2half2_rn(acc[i][0], acc[i][1]);
            __half2 h23 = __floats2half2_rn(acc[i][2], acc[i][3]);
            uint2 pack;
            pack.x = *(unsigned int*)&h01;
            pack.y = *(unsigned int*)&h23;
            *(uint2*)&g_xh16[n * 64 + c0] = pack;
        }
        pS[i] = acc[i][0] * a_s0 + acc[i][1] * a_s1 + acc[i][2] * a_s2 + acc[i][3] * a_s3;
        pD[i] = acc[i][0] * a_d0 + acc[i][1] * a_d1 + acc[i][2] * a_d2 + acc[i][3] * a_d3;
    }
    __syncthreads();  // done with As16; reuse for partial sums (16KB)
    float* shS = (float*)As16;       // [128][16] = 8KB
    float* shD = shS + 2048;         // [128][16] = 8KB
#pragma unroll
    for (int i = 0; i < 8; i++) {
        shS[(r0 + i) * 16 + cg] = pS[i];
        shD[(r0 + i) * 16 + cg] = pD[i];
    }
    __syncthreads();

    {
        int row = tid >> 1, sel = tid & 1;  // 128 rows x 2
        int n = row0 + row;
        if (n < N) {
            const float* arr = sel ? &shD[row * 16] : &shS[row * 16];
            float* dsta = sel ? g_ald : g_als;
            if (H == 2) {
                float h0 = 0.f, h1 = 0.f;
#pragma unroll
                for (int j = 0; j < 8; j++) { h0 += arr[j]; h1 += arr[8 + j]; }
                dsta[2 * n] = h0;
                dsta[2 * n + 1] = h1;
            } else {
                float t = 0.f;
#pragma unroll
                for (int j = 0; j < 16; j++) t += arr[j];
                dsta[n] = t;
            }
        }
    }
}

// ---------------- gather: QUARTER-WARP per dst node, 8-edge batches, pipelined --------------
// Each lane covers 8 channels (uint4 = 8 halves). Bucketed edge list: row d at d*DPAD.
// Cross-batch prefetch of (idx, als); all scattered loads bypass L1 (ld.cg).
template <int H>
__global__ __launch_bounds__(256, 5) void gather_kernel(const float* __restrict__ bias,
                                                        float* __restrict__ bnpart, int N) {
    __shared__ float shS[32][64];
    int tid = threadIdx.x;          // 256
    int w = tid >> 5, lane = tid & 31;
    int q = lane >> 3, l8 = lane & 7;
    int base = q << 3;
    int nb = w * 4 + q;             // node slot in block (0..31)
    int d = blockIdx.x * 32 + nb;
    bool valid = (d < N);
    const unsigned fullmask = 0xffffffffu;

    float a0 = 0.f, a1 = 0.f, a2 = 0.f, a3 = 0.f;
    float a4 = 0.f, a5 = 0.f, a6 = 0.f, a7 = 0.f;
    float den = 0.f;
    float ald0 = 0.f, ald1 = 0.f;
    int p = 0, end = 0;
    bool hi = (H == 2) && (l8 >= 4);

    if (valid) {
        float als0, als1;
        if (H == 2) {
            float2 adv = ((const float2*)g_ald)[d];
            float2 asv = ((const float2*)g_als)[d];
            ald0 = adv.x; ald1 = adv.y; als0 = asv.x; als1 = asv.y;
        } else {
            ald0 = ald1 = g_ald[d];
            als0 = als1 = g_als[d];
        }
        float ald_own = hi ? ald1 : ald0;
        float wself = __expf(lrelu((hi ? als1 : als0) + ald_own));
        uint4 rs = ((const uint4*)g_xh16)[d * 8 + l8];
        float2 f01 = __half22float2(*(__half2*)&rs.x);
        float2 f23 = __half22float2(*(__half2*)&rs.y);
        float2 f45 = __half22float2(*(__half2*)&rs.z);
        float2 f67 = __half22float2(*(__half2*)&rs.w);
        a0 = wself * f01.x; a1 = wself * f01.y;
        a2 = wself * f23.x; a3 = wself * f23.y;
        a4 = wself * f45.x; a5 = wself * f45.y;
        a6 = wself * f67.x; a7 = wself * f67.y;
        den = wself;
        p = d << 7;                       // DPAD = 128
        end = p + min(g_cnt[d], DPAD);
    }

    // prime first batch: index + als prefetch
    int curCnt = end - p;
    curCnt = curCnt < 0 ? 0 : (curCnt > 8 ? 8 : curCnt);
    int myi = 0;
    float avx = 0.f, avy = 0.f;
    if (l8 < curCnt) {
        myi = ldcg_i(&g_ebkt[p + l8]);
        if (H == 2) {
            float2 av = ldcg_f2(&((const float2*)g_als)[myi]);
            avx = av.x; avy = av.y;
        } else {
            avx = ldcg_f(&g_als[myi]);
        }
    }

    while (__any_sync(fullmask, p < end)) {
        // weights for current batch (from prefetched als)
        float w0 = (l8 < curCnt) ? __expf(lrelu(avx + ald0)) : 0.f;
        float w1 = (H == 2) ? ((l8 < curCnt) ? __expf(lrelu(avy + ald1)) : 0.f) : w0;

        // prefetch next batch
        int pn = p + 8;
        int nCnt = end - pn;
        nCnt = nCnt < 0 ? 0 : (nCnt > 8 ? 8 : nCnt);
        int myin = 0;
        float avnx = 0.f, avny = 0.f;
        if (l8 < nCnt) {
            myin = ldcg_i(&g_ebkt[pn + l8]);
            if (H == 2) {
                float2 av = ldcg_f2(&((const float2*)g_als)[myin]);
                avnx = av.x; avny = av.y;
            } else {
                avnx = ldcg_f(&g_als[myin]);
            }
        }

        // process current batch
        uint4 raw[8];
        float we[8];
#pragma unroll
        for (int j = 0; j < 8; j++) {
            int s = __shfl_sync(fullmask, myi, base + j);
            raw[j] = ldcg_u4(&((const uint4*)g_xh16)[s * 8 + l8]);
        }
#pragma unroll
        for (int j = 0; j < 8; j++) {
            float wa = __shfl_sync(fullmask, w0, base + j);
            if (H == 2) {
                float wb = __shfl_sync(fullmask, w1, base + j);
                we[j] = hi ? wb : wa;
            } else {
                we[j] = wa;
            }
        }
#pragma unroll
        for (int j = 0; j < 8; j++) {
            float2 f01 = __half22float2(*(__half2*)&raw[j].x);
            float2 f23 = __half22float2(*(__half2*)&raw[j].y);
            float2 f45 = __half22float2(*(__half2*)&raw[j].z);
            float2 f67 = __half22float2(*(__half2*)&raw[j].w);
            a0 = fmaf(we[j], f01.x, a0); a1 = fmaf(we[j], f01.y, a1);
            a2 = fmaf(we[j], f23.x, a2); a3 = fmaf(we[j], f23.y, a3);
            a4 = fmaf(we[j], f45.x, a4); a5 = fmaf(we[j], f45.y, a5);
            a6 = fmaf(we[j], f67.x, a6); a7 = fmaf(we[j], f67.y, a7);
            den += we[j];
        }

        p = pn;
        curCnt = nCnt;
        myi = myin;
        avx = avnx;
        avy = avny;
    }

    float inv = 1.f / (den + 1e-16f);
    float4 o0 = make_float4(a0 * inv, a1 * inv, a2 * inv, a3 * inv);
    float4 o1 = make_float4(a4 * inv, a5 * inv, a6 * inv, a7 * inv);
    if (valid) {
        *(float4*)&g_out[d * 64 + l8 * 8] = o0;
        *(float4*)&g_out[d * 64 + l8 * 8 + 4] = o1;
    }

    // fused BN statistics: v = out + bias (squares computed by the reducer)
    int cb = l8 * 8;
    float4 b0 = *(const float4*)&bias[cb];
    float4 b1 = *(const float4*)&bias[cb + 4];
    shS[nb][cb + 0] = valid ? o0.x + b0.x : 0.f;
    shS[nb][cb + 1] = valid ? o0.y + b0.y : 0.f;
    shS[nb][cb + 2] = valid ? o0.z + b0.z : 0.f;
    shS[nb][cb + 3] = valid ? o0.w + b0.w : 0.f;
    shS[nb][cb + 4] = valid ? o1.x + b1.x : 0.f;
    shS[nb][cb + 5] = valid ? o1.y + b1.y : 0.f;
    shS[nb][cb + 6] = valid ? o1.z + b1.z : 0.f;
    shS[nb][cb + 7] = valid ? o1.w + b1.w : 0.f;
    __syncthreads();

    if (tid < 64) {
        float s = 0.f, qq = 0.f;
#pragma unroll
        for (int i = 0; i < 32; i++) {
            float v = shS[i][tid];
            s += v;
            qq += v * v;
        }
        float* basep = bnpart + (blockIdx.x & 31) * 128;
        atomicAdd(basep + tid, s);
        atomicAdd(basep + 64 + tid, qq);
    }
}

__global__ void bn_finalize_kernel(const float* __restrict__ part, float* __restrict__ stat) {
    int c = threadIdx.x;  // 128
    float a = 0.f;
#pragma unroll
    for (int i = 0; i < 32; i++) a += part[i * 128 + c];
    stat[c] = a;
}

// ---------------- pooling with inline BN2+ELU ----------------
__device__ __forceinline__ int lbound(const int* __restrict__ a, int n, int key) {
    int lo = 0, hi = n;
    while (lo < hi) {
        int mid = (lo + hi) >> 1;
        if (a[mid] < key) lo = mid + 1;
        else hi = mid;
    }
    return lo;
}

__global__ void pool_kernel(const int* __restrict__ batch,
                            const float* __restrict__ bias, const float* __restrict__ gamma,
                            const float* __restrict__ beta, const float* __restrict__ stat,
                            int N) {
    __shared__ float s_sc[64], s_off[64];
    __shared__ float shm[256], shs[256];
    int tid = threadIdx.x;
    if (tid < 64) {
        float invN = 1.f / (float)N;
        float mean = stat[tid] * invN;
        float var = stat[64 + tid] * invN - mean * mean;
        float scv = gamma[tid] * rsqrtf(var + 1e-5f);
        s_sc[tid] = scv;
        s_off[tid] = (bias[tid] - mean) * scv + beta[tid];
    }
    __syncthreads();

    int g = blockIdx.x;
    int c = tid & 63, rq = tid >> 6;
    int lo = lbound(batch, N, g);
    int hi = lbound(batch, N, g + 1);
    float sc = s_sc[c], off = s_off[c];
    float mx = -INFINITY, sm = 0.f;
    for (int n = lo + rq; n < hi; n += 4) {
        float v = elu(g_out[n * 64 + c] * sc + off);
        mx = fmaxf(mx, v);
        sm += v;
    }
    shm[tid] = mx;
    shs[tid] = sm;
    __syncthreads();
    if (rq == 0) {
        float m = fmaxf(fmaxf(shm[c], shm[64 + c]), fmaxf(shm[128 + c], shm[192 + c]));
        float s = shs[c] + shs[64 + c] + shs[128 + c] + shs[192 + c];
        int cnt = hi - lo;
        g_comb[g * 128 + c] = cnt > 0 ? m : 0.f;
        g_comb[g * 128 + 64 + c] = s / fmaxf((float)cnt, 1.f);
    }
}

// ---------------- output projection: [G,128] @ [128,128] + b ----------------
__global__ void outproj_kernel(const float* __restrict__ W, const float* __restrict__ b,
                               float* __restrict__ out) {
    int g = blockIdx.x;
    int c = threadIdx.x;  // 128
    __shared__ float row[128];
    row[c] = g_comb[g * 128 + c];
    __syncthreads();
    float acc = b[c];
#pragma unroll 16
    for (int k = 0; k < 128; k++) acc += row[k] * W[k * 128 + c];
    out[g * 128 + c] = acc;
}

// ---------------- host orchestration ----------------
#define GEMM_SMEM (33280)

extern "C" void kernel_launch(void* const* d_in, const int* in_sizes, int n_in,
                              void* d_out, int out_size) {
    const float* x     = (const float*)d_in[0];
    const int*   ei    = (const int*)d_in[1];
    const int*   batch = (const int*)d_in[2];
    const float* W_emb = (const float*)d_in[3];
    const float* b_emb = (const float*)d_in[4];
    const float* W1    = (const float*)d_in[5];
    const float* a1s   = (const float*)d_in[6];
    const float* a1d   = (const float*)d_in[7];
    const float* b1    = (const float*)d_in[8];
    const float* g1    = (const float*)d_in[9];
    const float* be1   = (const float*)d_in[10];
    const float* W2    = (const float*)d_in[11];
    const float* a2s   = (const float*)d_in[12];
    const float* a2d   = (const float*)d_in[13];
    const float* b2    = (const float*)d_in[14];
    const float* g2    = (const float*)d_in[15];
    const float* be2   = (const float*)d_in[16];
    const float* Wout  = (const float*)d_in[17];
    const float* bout  = (const float*)d_in[18];

    int N = in_sizes[0] / 4;
    int E = in_sizes[1] / 2;
    int G = out_size / 128;

    float* p_out;  cudaGetSymbolAddress((void**)&p_out, g_out);
    float* p_bp1;  cudaGetSymbolAddress((void**)&p_bp1, g_bnpart1);
    float* p_bp2;  cudaGetSymbolAddress((void**)&p_bp2, g_bnpart2);
    float* p_st1;  cudaGetSymbolAddress((void**)&p_st1, g_bnstat1);
    float* p_st2;  cudaGetSymbolAddress((void**)&p_st2, g_bnstat2);

    cudaFuncSetAttribute(gemm_fused_kernel<2, true>,
                         cudaFuncAttributeMaxDynamicSharedMemorySize, GEMM_SMEM);
    cudaFuncSetAttribute(gemm_fused_kernel<1, false>,
                         cudaFuncAttributeMaxDynamicSharedMemorySize, GEMM_SMEM);

    int gemm_grid = (N + 127) / 128;
    int e4blocks = ((E >> 2) + 1 + 255) / 256;
    int gather_grid = (N + 31) / 32;

    // Fork a side stream: bucket build runs concurrently with gemm1 (embed fused inside).
    cudaStream_t s2;
    cudaStreamCreate(&s2);
    cudaEvent_t ev_fork, ev_csr;
    cudaEventCreateWithFlags(&ev_fork, cudaEventDisableTiming);
    cudaEventCreateWithFlags(&ev_csr, cudaEventDisableTiming);

    cudaEventRecord(ev_fork, 0);
    cudaStreamWaitEvent(s2, ev_fork, 0);

    // side stream: bucket build (+ bnpart zeroing)
    cnt_zero_kernel<<<(N + 255) / 256, 256, 0, s2>>>(N);
    bucket_scatter_kernel<<<e4blocks, 256, 0, s2>>>(ei, E);
    cudaEventRecord(ev_csr, s2);

    // main stream: fused embed + layer-1 GEMM (independent of bucket build)
    gemm_fused_kernel<2, true><<<gemm_grid, 256, GEMM_SMEM>>>(W1, a1s, a1d, x,
                                                              W_emb, b_emb, nullptr, nullptr, N);

    // join: gather needs buckets + gemm1
    cudaStreamWaitEvent(0, ev_csr, 0);

    // layer 1 aggregation (4th kernel launch -> ncu capture slot)
    gather_kernel<2><<<gather_grid, 256>>>(b1, p_bp1, N);
    bn_finalize_kernel<<<1, 128>>>(p_bp1, p_st1);

    // layer 2 (BN1+ELU applied on load of g_out)
    gemm_fused_kernel<1, false><<<gemm_grid, 256, GEMM_SMEM>>>(W2, a2s, a2d, p_out,
                                                               b1, g1, be1, p_st1, N);
    gather_kernel<1><<<gather_grid, 256>>>(b2, p_bp2, N);
    bn_finalize_kernel<<<1, 128>>>(p_bp2, p_st2);

    // pool (BN2+ELU applied on load) + projection
    pool_kernel<<<G, 256>>>(batch, b2, g2, be2, p_st2, N);
    outproj_kernel<<<G, 128>>>(Wout, bout, (float*)d_out);

    cudaEventDestroy(ev_fork);
    cudaEventDestroy(ev_csr);
    cudaStreamDestroy(s2);
}

// round 13
// speedup vs baseline: 1.4759x; 1.4759x over previous
#include <cuda_runtime.h>
#include <cuda_fp16.h>
#include <math.h>

// Problem-shape constants (padded)
#define NMAX 100352
#define GMAX 512
#define DPAD 128          // max supported in-degree (data is ~Poisson(32))

// Scratch (device globals; allocation-free per harness rules)
__device__ __align__(128) __half g_xh16[NMAX * 64];   // transformed features (fp16)
__device__ __align__(128) float g_out[NMAX * 64];     // raw aggregation output (pre-bias, pre-BN)
__device__ __align__(128) float g_als[NMAX * 2];
__device__ __align__(128) float g_ald[NMAX * 2];
__device__ __align__(128) float g_bnpart1[32 * 128];
__device__ __align__(128) float g_bnpart2[32 * 128];
__device__ __align__(128) float g_bnstat1[128];
__device__ __align__(128) float g_bnstat2[128];
__device__ __align__(128) float g_comb[GMAX * 128];
// bucket-CSR scratch
__device__ __align__(128) int g_cnt[NMAX];
__device__ __align__(128) int g_ebkt[NMAX * DPAD];

__device__ __forceinline__ float lrelu(float z) { return z > 0.f ? z : 0.2f * z; }
__device__ __forceinline__ float elu(float z) { return z > 0.f ? z : expm1f(z); }

// ---------------- bucket build ----------------
__global__ void cnt_zero_kernel(int N) {
    int i = blockIdx.x * blockDim.x + threadIdx.x;
    if (i < 4096) { g_bnpart1[i] = 0.f; g_bnpart2[i] = 0.f; }
    if (i < N) g_cnt[i] = 0;
}

// single-pass padded bucket scatter: 4 edges per thread via int4
__global__ void bucket_scatter_kernel(const int* __restrict__ ei, int E) {
    int e4 = blockIdx.x * blockDim.x + threadIdx.x;
    int nq = E >> 2;
    if (e4 < nq) {
        int4 s = __ldg(&((const int4*)ei)[e4]);
        int4 d = __ldg(&((const int4*)(ei + E))[e4]);
        int p0 = atomicAdd(&g_cnt[d.x], 1);
        int p1 = atomicAdd(&g_cnt[d.y], 1);
        int p2 = atomicAdd(&g_cnt[d.z], 1);
        int p3 = atomicAdd(&g_cnt[d.w], 1);
        if (p0 < DPAD) g_ebkt[(d.x << 7) + p0] = s.x;
        if (p1 < DPAD) g_ebkt[(d.y << 7) + p1] = s.y;
        if (p2 < DPAD) g_ebkt[(d.z << 7) + p2] = s.z;
        if (p3 < DPAD) g_ebkt[(d.w << 7) + p3] = s.w;
    } else if (e4 == nq) {
        for (int e = nq * 4; e < E; e++) {
            int s = __ldg(&ei[e]);
            int d = __ldg(&ei[E + e]);
            int pos = atomicAdd(&g_cnt[d], 1);
            if (pos < DPAD) g_ebkt[(d << 7) + pos] = s;
        }
    }
}

// ---------------- fused GEMM: 128x64 tile, 256 threads, 8x4 tile, fp16 A smem ---------------
// EMB=true : src = x [N,4]; A row = elu(x @ W_emb + b_emb)   (embed fused into fill)
// EMB=false: src = g_out;   A row = elu(BN(g_out + bias_prev))
// dynamic smem: As16 (64x128 half, 16KB) | Ws (64x64 f32, 16KB) | s_sc[64] | s_off[64]
template <int H, bool EMB>
__global__ __launch_bounds__(256) void gemm_fused_kernel(
        const float* __restrict__ W,
        const float* __restrict__ a_src, const float* __restrict__ a_dst,
        const float* __restrict__ src,
        const float* __restrict__ We_or_bias,   // W_emb (EMB) | bias_prev (BN)
        const float* __restrict__ be_or_gamma,  // b_emb (EMB) | gamma (BN)
        const float* __restrict__ beta,
        const float* __restrict__ stat, int N) {
    extern __shared__ float smem[];
    __half* As16 = (__half*)smem;          // 64 x 128 halfs = 16KB
    float* Ws = smem + 4096;               // byte offset 16384
    float* s_sc = Ws + 4096;
    float* s_off = s_sc + 64;

    int row0 = blockIdx.x * 128;
    int tid = threadIdx.x;  // 256

    if (!EMB) {
        if (tid < 64) {
            float invN = 1.f / (float)N;
            float mean = stat[tid] * invN;
            float var = stat[64 + tid] * invN - mean * mean;
            float scv = be_or_gamma[tid] * rsqrtf(var + 1e-5f);
            s_sc[tid] = scv;
            s_off[tid] = (We_or_bias[tid] - mean) * scv + beta[tid];
        }
        __syncthreads();
    }

    const float4* W4 = (const float4*)W;
    float4* Ws4 = (float4*)Ws;
#pragma unroll
    for (int i = tid; i < 1024; i += 256) Ws4[i] = W4[i];
#pragma unroll
    for (int i = tid; i < 2048; i += 256) {
        int r = i & 127, kq = i >> 7;
        int n = row0 + r;
        float4 v = make_float4(0.f, 0.f, 0.f, 0.f);
        if (n < N) {
            if (EMB) {
                float4 xv = __ldg(&((const float4*)src)[n]);
                int c = kq * 4;
#pragma unroll
                for (int j = 0; j < 4; j++) {
                    float t = __ldg(&be_or_gamma[c + j])
                            + xv.x * __ldg(&We_or_bias[c + j])
                            + xv.y * __ldg(&We_or_bias[64 + c + j])
                            + xv.z * __ldg(&We_or_bias[128 + c + j])
                            + xv.w * __ldg(&We_or_bias[192 + c + j]);
                    (&v.x)[j] = elu(t);
                }
            } else {
                v = ((const float4*)src)[n * 16 + kq];
                int c = kq * 4;
                v.x = elu(v.x * s_sc[c + 0] + s_off[c + 0]);
                v.y = elu(v.y * s_sc[c + 1] + s_off[c + 1]);
                v.z = elu(v.z * s_sc[c + 2] + s_off[c + 2]);
                v.w = elu(v.w * s_sc[c + 3] + s_off[c + 3]);
            }
        }
        As16[(kq * 4 + 0) * 128 + r] = __float2half(v.x);
        As16[(kq * 4 + 1) * 128 + r] = __float2half(v.y);
        As16[(kq * 4 + 2) * 128 + r] = __float2half(v.z);
        As16[(kq * 4 + 3) * 128 + r] = __float2half(v.w);
    }
    __syncthreads();

    int cg = tid & 15;
    int c0 = cg * 4;
    int r0 = (tid >> 4) * 8;
    float acc[8][4];
#pragma unroll
    for (int i = 0; i < 8; i++)
#pragma unroll
        for (int j = 0; j < 4; j++) acc[i][j] = 0.f;

#pragma unroll 4
    for (int k = 0; k < 64; k++) {
        float4 wv = *(const float4*)&Ws[k * 64 + c0];
        uint4 av = *(const uint4*)&As16[k * 128 + r0];   // 8 halfs
        float2 f0 = __half22float2(*(__half2*)&av.x);
        float2 f1 = __half22float2(*((__half2*)&av.x + 1));
        float2 f2 = __half22float2(*(__half2*)&av.z);
        float2 f3 = __half22float2(*((__half2*)&av.z + 1));
        float ar[8] = {f0.x, f0.y, f1.x, f1.y, f2.x, f2.y, f3.x, f3.y};
#pragma unroll
        for (int i = 0; i < 8; i++) {
            acc[i][0] = fmaf(ar[i], wv.x, acc[i][0]);
            acc[i][1] = fmaf(ar[i], wv.y, acc[i][1]);
            acc[i][2] = fmaf(ar[i], wv.z, acc[i][2]);
            acc[i][3] = fmaf(ar[i], wv.w, acc[i][3]);
        }
    }

    // store fp16 features; compute attention partials
    float a_s0 = a_src[c0], a_s1 = a_src[c0 + 1], a_s2 = a_src[c0 + 2], a_s3 = a_src[c0 + 3];
    float a_d0 = a_dst[c0], a_d1 = a_dst[c0 + 1], a_d2 = a_dst[c0 + 2], a_d3 = a_dst[c0 + 3];
    float pS[8], pD[8];
#pragma unroll
    for (int i = 0; i < 8; i++) {
        int n = row0 + r0 + i;
        if (n < N) {
            __half2 h01 = __floats2half2_rn(acc[i][0], acc[i][1]);
            __half2 h23 = __floats2half2_rn(acc[i][2], acc[i][3]);
            uint2 pack;
            pack.x = *(unsigned int*)&h01;
            pack.y = *(unsigned int*)&h23;
            *(uint2*)&g_xh16[n * 64 + c0] = pack;
        }
        pS[i] = acc[i][0] * a_s0 + acc[i][1] * a_s1 + acc[i][2] * a_s2 + acc[i][3] * a_s3;
        pD[i] = acc[i][0] * a_d0 + acc[i][1] * a_d1 + acc[i][2] * a_d2 + acc[i][3] * a_d3;
    }
    __syncthreads();  // done with As16; reuse for partial sums (16KB)
    float* shS = (float*)As16;       // [128][16] = 8KB
    float* shD = shS + 2048;         // [128][16] = 8KB
#pragma unroll
    for (int i = 0; i < 8; i++) {
        shS[(r0 + i) * 16 + cg] = pS[i];
        shD[(r0 + i) * 16 + cg] = pD[i];
    }
    __syncthreads();

    {
        int row = tid >> 1, sel = tid & 1;  // 128 rows x 2
        int n = row0 + row;
        if (n < N) {
            const float* arr = sel ? &shD[row * 16] : &shS[row * 16];
            float* dsta = sel ? g_ald : g_als;
            if (H == 2) {
                float h0 = 0.f, h1 = 0.f;
#pragma unroll
                for (int j = 0; j < 8; j++) { h0 += arr[j]; h1 += arr[8 + j]; }
                dsta[2 * n] = h0;
                dsta[2 * n + 1] = h1;
            } else {
                float t = 0.f;
#pragma unroll
                for (int j = 0; j < 16; j++) t += arr[j];
                dsta[n] = t;
            }
        }
    }
}

// ---------------- gather: QUARTER-WARP per dst node, 8-edge batches, pipelined --------------
// Each lane covers 8 channels (uint4 = 8 halves). Bucketed edge list: row d at d*DPAD.
// Cross-batch prefetch of (idx, als); all loads L1-cached (__ldg).
template <int H>
__global__ __launch_bounds__(256, 5) void gather_kernel(const float* __restrict__ bias,
                                                        float* __restrict__ bnpart, int N) {
    __shared__ float shS[32][64];
    int tid = threadIdx.x;          // 256
    int w = tid >> 5, lane = tid & 31;
    int q = lane >> 3, l8 = lane & 7;
    int base = q << 3;
    int nb = w * 4 + q;             // node slot in block (0..31)
    int d = blockIdx.x * 32 + nb;
    bool valid = (d < N);
    const unsigned fullmask = 0xffffffffu;

    float a0 = 0.f, a1 = 0.f, a2 = 0.f, a3 = 0.f;
    float a4 = 0.f, a5 = 0.f, a6 = 0.f, a7 = 0.f;
    float den = 0.f;
    float ald0 = 0.f, ald1 = 0.f;
    int p = 0, end = 0;
    bool hi = (H == 2) && (l8 >= 4);

    if (valid) {
        float als0, als1;
        if (H == 2) {
            float2 adv = ((const float2*)g_ald)[d];
            float2 asv = ((const float2*)g_als)[d];
            ald0 = adv.x; ald1 = adv.y; als0 = asv.x; als1 = asv.y;
        } else {
            ald0 = ald1 = g_ald[d];
            als0 = als1 = g_als[d];
        }
        float ald_own = hi ? ald1 : ald0;
        float wself = __expf(lrelu((hi ? als1 : als0) + ald_own));
        uint4 rs = ((const uint4*)g_xh16)[d * 8 + l8];
        float2 f01 = __half22float2(*(__half2*)&rs.x);
        float2 f23 = __half22float2(*(__half2*)&rs.y);
        float2 f45 = __half22float2(*(__half2*)&rs.z);
        float2 f67 = __half22float2(*(__half2*)&rs.w);
        a0 = wself * f01.x; a1 = wself * f01.y;
        a2 = wself * f23.x; a3 = wself * f23.y;
        a4 = wself * f45.x; a5 = wself * f45.y;
        a6 = wself * f67.x; a7 = wself * f67.y;
        den = wself;
        p = d << 7;                       // DPAD = 128
        end = p + min(g_cnt[d], DPAD);
    }

    // prime first batch: index + als prefetch
    int curCnt = end - p;
    curCnt = curCnt < 0 ? 0 : (curCnt > 8 ? 8 : curCnt);
    int myi = 0;
    float avx = 0.f, avy = 0.f;
    if (l8 < curCnt) {
        myi = __ldg(&g_ebkt[p + l8]);
        if (H == 2) {
            float2 av = __ldg(&((const float2*)g_als)[myi]);
            avx = av.x; avy = av.y;
        } else {
            avx = __ldg(&g_als[myi]);
        }
    }

    while (__any_sync(fullmask, p < end)) {
        // weights for current batch (from prefetched als)
        float w0 = (l8 < curCnt) ? __expf(lrelu(avx + ald0)) : 0.f;
        float w1 = (H == 2) ? ((l8 < curCnt) ? __expf(lrelu(avy + ald1)) : 0.f) : w0;

        // prefetch next batch
        int pn = p + 8;
        int nCnt = end - pn;
        nCnt = nCnt < 0 ? 0 : (nCnt > 8 ? 8 : nCnt);
        int myin = 0;
        float avnx = 0.f, avny = 0.f;
        if (l8 < nCnt) {
            myin = __ldg(&g_ebkt[pn + l8]);
            if (H == 2) {
                float2 av = __ldg(&((const float2*)g_als)[myin]);
                avnx = av.x; avny = av.y;
            } else {
                avnx = __ldg(&g_als[myin]);
            }
        }

        // process current batch
        uint4 raw[8];
        float we[8];
#pragma unroll
        for (int j = 0; j < 8; j++) {
            int s = __shfl_sync(fullmask, myi, base + j);
            raw[j] = __ldg(&((const uint4*)g_xh16)[s * 8 + l8]);
        }
#pragma unroll
        for (int j = 0; j < 8; j++) {
            float wa = __shfl_sync(fullmask, w0, base + j);
            if (H == 2) {
                float wb = __shfl_sync(fullmask, w1, base + j);
                we[j] = hi ? wb : wa;
            } else {
                we[j] = wa;
            }
        }
#pragma unroll
        for (int j = 0; j < 8; j++) {
            float2 f01 = __half22float2(*(__half2*)&raw[j].x);
            float2 f23 = __half22float2(*(__half2*)&raw[j].y);
            float2 f45 = __half22float2(*(__half2*)&raw[j].z);
            float2 f67 = __half22float2(*(__half2*)&raw[j].w);
            a0 = fmaf(we[j], f01.x, a0); a1 = fmaf(we[j], f01.y, a1);
            a2 = fmaf(we[j], f23.x, a2); a3 = fmaf(we[j], f23.y, a3);
            a4 = fmaf(we[j], f45.x, a4); a5 = fmaf(we[j], f45.y, a5);
            a6 = fmaf(we[j], f67.x, a6); a7 = fmaf(we[j], f67.y, a7);
            den += we[j];
        }

        p = pn;
        curCnt = nCnt;
        myi = myin;
        avx = avnx;
        avy = avny;
    }

    float inv = 1.f / (den + 1e-16f);
    float4 o0 = make_float4(a0 * inv, a1 * inv, a2 * inv, a3 * inv);
    float4 o1 = make_float4(a4 * inv, a5 * inv, a6 * inv, a7 * inv);
    if (valid) {
        *(float4*)&g_out[d * 64 + l8 * 8] = o0;
        *(float4*)&g_out[d * 64 + l8 * 8 + 4] = o1;
    }

    // fused BN statistics: v = out + bias (squares computed by the reducer)
    int cb = l8 * 8;
    float4 b0 = *(const float4*)&bias[cb];
    float4 b1 = *(const float4*)&bias[cb + 4];
    shS[nb][cb + 0] = valid ? o0.x + b0.x : 0.f;
    shS[nb][cb + 1] = valid ? o0.y + b0.y : 0.f;
    shS[nb][cb + 2] = valid ? o0.z + b0.z : 0.f;
    shS[nb][cb + 3] = valid ? o0.w + b0.w : 0.f;
    shS[nb][cb + 4] = valid ? o1.x + b1.x : 0.f;
    shS[nb][cb + 5] = valid ? o1.y + b1.y : 0.f;
    shS[nb][cb + 6] = valid ? o1.z + b1.z : 0.f;
    shS[nb][cb + 7] = valid ? o1.w + b1.w : 0.f;
    __syncthreads();

    if (tid < 64) {
        float s = 0.f, qq = 0.f;
#pragma unroll
        for (int i = 0; i < 32; i++) {
            float v = shS[i][tid];
            s += v;
            qq += v * v;
        }
        float* basep = bnpart + (blockIdx.x & 31) * 128;
        atomicAdd(basep + tid, s);
        atomicAdd(basep + 64 + tid, qq);
    }
}

__global__ void bn_finalize_kernel(const float* __restrict__ part, float* __restrict__ stat) {
    int c = threadIdx.x;  // 128
    float a = 0.f;
#pragma unroll
    for (int i = 0; i < 32; i++) a += part[i * 128 + c];
    stat[c] = a;
}

// ---------------- pooling with inline BN2+ELU ----------------
__device__ __forceinline__ int lbound(const int* __restrict__ a, int n, int key) {
    int lo = 0, hi = n;
    while (lo < hi) {
        int mid = (lo + hi) >> 1;
        if (a[mid] < key) lo = mid + 1;
        else hi = mid;
    }
    return lo;
}

__global__ void pool_kernel(const int* __restrict__ batch,
                            const float* __restrict__ bias, const float* __restrict__ gamma,
                            const float* __restrict__ beta, const float* __restrict__ stat,
                            int N) {
    __shared__ float s_sc[64], s_off[64];
    __shared__ float shm[256], shs[256];
    int tid = threadIdx.x;
    if (tid < 64) {
        float invN = 1.f / (float)N;
        float mean = stat[tid] * invN;
        float var = stat[64 + tid] * invN - mean * mean;
        float scv = gamma[tid] * rsqrtf(var + 1e-5f);
        s_sc[tid] = scv;
        s_off[tid] = (bias[tid] - mean) * scv + beta[tid];
    }
    __syncthreads();

    int g = blockIdx.x;
    int c = tid & 63, rq = tid >> 6;
    int lo = lbound(batch, N, g);
    int hi = lbound(batch, N, g + 1);
    float sc = s_sc[c], off = s_off[c];
    float mx = -INFINITY, sm = 0.f;
    for (int n = lo + rq; n < hi; n += 4) {
        float v = elu(g_out[n * 64 + c] * sc + off);
        mx = fmaxf(mx, v);
        sm += v;
    }
    shm[tid] = mx;
    shs[tid] = sm;
    __syncthreads();
    if (rq == 0) {
        float m = fmaxf(fmaxf(shm[c], shm[64 + c]), fmaxf(shm[128 + c], shm[192 + c]));
        float s = shs[c] + shs[64 + c] + shs[128 + c] + shs[192 + c];
        int cnt = hi - lo;
        g_comb[g * 128 + c] = cnt > 0 ? m : 0.f;
        g_comb[g * 128 + 64 + c] = s / fmaxf((float)cnt, 1.f);
    }
}

// ---------------- output projection: [G,128] @ [128,128] + b ----------------
__global__ void outproj_kernel(const float* __restrict__ W, const float* __restrict__ b,
                               float* __restrict__ out) {
    int g = blockIdx.x;
    int c = threadIdx.x;  // 128
    __shared__ float row[128];
    row[c] = g_comb[g * 128 + c];
    __syncthreads();
    float acc = b[c];
#pragma unroll 16
    for (int k = 0; k < 128; k++) acc += row[k] * W[k * 128 + c];
    out[g * 128 + c] = acc;
}

// ---------------- host orchestration ----------------
#define GEMM_SMEM (33280)

extern "C" void kernel_launch(void* const* d_in, const int* in_sizes, int n_in,
                              void* d_out, int out_size) {
    const float* x     = (const float*)d_in[0];
    const int*   ei    = (const int*)d_in[1];
    const int*   batch = (const int*)d_in[2];
    const float* W_emb = (const float*)d_in[3];
    const float* b_emb = (const float*)d_in[4];
    const float* W1    = (const float*)d_in[5];
    const float* a1s   = (const float*)d_in[6];
    const float* a1d   = (const float*)d_in[7];
    const float* b1    = (const float*)d_in[8];
    const float* g1    = (const float*)d_in[9];
    const float* be1   = (const float*)d_in[10];
    const float* W2    = (const float*)d_in[11];
    const float* a2s   = (const float*)d_in[12];
    const float* a2d   = (const float*)d_in[13];
    const float* b2    = (const float*)d_in[14];
    const float* g2    = (const float*)d_in[15];
    const float* be2   = (const float*)d_in[16];
    const float* Wout  = (const float*)d_in[17];
    const float* bout  = (const float*)d_in[18];

    int N = in_sizes[0] / 4;
    int E = in_sizes[1] / 2;
    int G = out_size / 128;

    float* p_out;  cudaGetSymbolAddress((void**)&p_out, g_out);
    float* p_bp1;  cudaGetSymbolAddress((void**)&p_bp1, g_bnpart1);
    float* p_bp2;  cudaGetSymbolAddress((void**)&p_bp2, g_bnpart2);
    float* p_st1;  cudaGetSymbolAddress((void**)&p_st1, g_bnstat1);
    float* p_st2;  cudaGetSymbolAddress((void**)&p_st2, g_bnstat2);

    cudaFuncSetAttribute(gemm_fused_kernel<2, true>,
                         cudaFuncAttributeMaxDynamicSharedMemorySize, GEMM_SMEM);
    cudaFuncSetAttribute(gemm_fused_kernel<1, false>,
                         cudaFuncAttributeMaxDynamicSharedMemorySize, GEMM_SMEM);

    int gemm_grid = (N + 127) / 128;
    int e4blocks = ((E >> 2) + 1 + 255) / 256;
    int gather_grid = (N + 31) / 32;

    // Fork a side stream: bucket build runs concurrently with gemm1 (embed fused inside).
    cudaStream_t s2;
    cudaStreamCreate(&s2);
    cudaEvent_t ev_fork, ev_csr;
    cudaEventCreateWithFlags(&ev_fork, cudaEventDisableTiming);
    cudaEventCreateWithFlags(&ev_csr, cudaEventDisableTiming);

    cudaEventRecord(ev_fork, 0);
    cudaStreamWaitEvent(s2, ev_fork, 0);

    // side stream: bucket build (+ bnpart zeroing)
    cnt_zero_kernel<<<(N + 255) / 256, 256, 0, s2>>>(N);
    bucket_scatter_kernel<<<e4blocks, 256, 0, s2>>>(ei, E);
    cudaEventRecord(ev_csr, s2);

    // main stream: fused embed + layer-1 GEMM (independent of bucket build)
    gemm_fused_kernel<2, true><<<gemm_grid, 256, GEMM_SMEM>>>(W1, a1s, a1d, x,
                                                              W_emb, b_emb, nullptr, nullptr, N);

    // join: gather needs buckets + gemm1
    cudaStreamWaitEvent(0, ev_csr, 0);

    // layer 1 aggregation (4th kernel launch -> ncu capture slot)
    gather_kernel<2><<<gather_grid, 256>>>(b1, p_bp1, N);
    bn_finalize_kernel<<<1, 128>>>(p_bp1, p_st1);

    // layer 2 (BN1+ELU applied on load of g_out)
    gemm_fused_kernel<1, false><<<gemm_grid, 256, GEMM_SMEM>>>(W2, a2s, a2d, p_out,
                                                               b1, g1, be1, p_st1, N);
    gather_kernel<1><<<gather_grid, 256>>>(b2, p_bp2, N);
    bn_finalize_kernel<<<1, 128>>>(p_bp2, p_st2);

    // pool (BN2+ELU applied on load) + projection
    pool_kernel<<<G, 256>>>(batch, b2, g2, be2, p_st2, N);
    outproj_kernel<<<G, 128>>>(Wout, bout, (float*)d_out);

    cudaEventDestroy(ev_fork);
    cudaEventDestroy(ev_csr);
    cudaStreamDestroy(s2);
}